// round 7
// baseline (speedup 1.0000x reference)
#include <cuda_runtime.h>
#include <cuda_bf16.h>
#include <math.h>

#define HWSZ   19200
#define IMW    160
#define NPIX   2400
#define NBLKX  75          // 19200 / 256 cell blocks
#define NCOBJ  7           // object classes 1..7
#define NSTAGE 10          // staging blocks (10*256 >= 2400)

typedef unsigned long long ull;

// ---------------- packed f32x2 helpers ----------------
__device__ __forceinline__ ull pk2(float lo, float hi) {
    ull r; asm("mov.b64 %0, {%1, %2};" : "=l"(r) : "f"(lo), "f"(hi)); return r;
}
__device__ __forceinline__ void up2(ull v, float& lo, float& hi) {
    asm("mov.b64 {%0, %1}, %2;" : "=f"(lo), "=f"(hi) : "l"(v));
}
__device__ __forceinline__ ull add2(ull a, ull b) {
    ull r; asm("add.rn.f32x2 %0, %1, %2;" : "=l"(r) : "l"(a), "l"(b)); return r;
}
__device__ __forceinline__ ull mul2(ull a, ull b) {
    ull r; asm("mul.rn.f32x2 %0, %1, %2;" : "=l"(r) : "l"(a), "l"(b)); return r;
}
__device__ __forceinline__ ull fma2(ull a, ull b, ull c) {
    ull r; asm("fma.rn.f32x2 %0, %1, %2, %3;" : "=l"(r) : "l"(a), "l"(b), "l"(c)); return r;
}

// ---------------- scratch ----------------
__device__ __align__(16) float4 g_rec[NPIX];     // xs, ys, nx', ny'  (staging)
__device__ float  g_dep[NPIX];                   // exp(vz)
__device__ __align__(16) int g_cls[NPIX];        // effective class (0 = no vote)

__device__ __align__(16) float g_xy[NCOBJ][4800];
__device__ __align__(16) float g_nn[NCOBJ][4800];
__device__ __align__(8)  float g_dp[NCOBJ][2400];
__device__ int   g_cnt[NCOBJ];
__device__ int   g_npair[NCOBJ];
__device__ int   g_pv[NCOBJ * NBLKX];
__device__ int   g_pl[NCOBJ * NBLKX];
__device__ float g_pds[NCOBJ * NBLKX];

__device__ unsigned g_ctr1 = 0;                  // arrival counters (self-resetting)
__device__ unsigned g_ctr2 = 0;

struct P4 { ull a, b; };

// ============================================================================
// Kernel 1: stage (all blocks) + compact (last-arriving block)
// ============================================================================
__global__ void __launch_bounds__(256) stage_compact_kernel(const int* __restrict__ labels,
                                                            const int* __restrict__ masks,
                                                            const float* __restrict__ vp)
{
    const int tid = threadIdx.x, lane = tid & 31, warp = tid >> 5;
    const int i = blockIdx.x * 256 + tid;

    // ---- stage: one thread per sampled pixel ----
    if (i < NPIX) {
        const int idx = i * 8;
        const int lab = labels[idx];
        const int msk = masks[idx];
        const int c = (msk > 0 && lab > 0) ? lab : 0;
        g_cls[i] = c;
        if (c) {
            const float vx = vp[(c * 3 + 0) * HWSZ + idx];
            const float vy = vp[(c * 3 + 1) * HWSZ + idx];
            const float vz = vp[(c * 3 + 2) * HWSZ + idx];
            const float nrm = sqrtf(vx * vx + vy * vy) + 1e-6f;
            const float nxp = (vx / nrm) * (1.0f / 0.9f);
            const float nyp = (vy / nrm) * (1.0f / 0.9f);
            g_rec[i] = make_float4((float)(idx % IMW), (float)(idx / IMW), nxp, nyp);
            g_dep[i] = expf(vz);
        }
    }

    // ---- arrival: last block performs compaction ----
    __threadfence();
    __syncthreads();
    __shared__ __align__(16) int s_cls[NPIX];    // 16-aligned for int4 vector loads
    __shared__ unsigned s_old;
    if (tid == 0) s_old = atomicAdd(&g_ctr1, 1u);
    __syncthreads();
    if (s_old != NSTAGE - 1) return;
    __threadfence();   // make other blocks' staging writes ordered before our reads

    const int4* gc4 = (const int4*)g_cls;
    int4* sc4 = (int4*)s_cls;
    #pragma unroll
    for (int k = 0; k < 3; k++) {
        int j = k * 256 + tid;
        if (j < NPIX / 4) sc4[j] = gc4[j];
    }
    __syncthreads();

    if (warp < NCOBJ) {
        const int myc = warp + 1;
        const unsigned below = (1u << lane) - 1u;
        int base = 0;
        #pragma unroll 5
        for (int it = 0; it < 75; it++) {
            const int ii = it * 32 + lane;
            const bool pred = (s_cls[ii] == myc);
            const unsigned bal = __ballot_sync(0xFFFFFFFFu, pred);
            if (pred) {
                const float4 r = g_rec[ii];    // L2 hit
                const float  d = g_dep[ii];
                const int slot = base + __popc(bal & below);
                const int p = slot >> 1, h = slot & 1;
                g_xy[warp][p * 4 + h]     = -r.x;
                g_xy[warp][p * 4 + 2 + h] = -r.y;
                g_nn[warp][p * 4 + h]     = r.z;
                g_nn[warp][p * 4 + 2 + h] = r.w;
                g_dp[warp][p * 2 + h]     = d;
            }
            base += __popc(bal);
        }
        const int pad = (base + 7) & ~7;      // pad: never-inlier dummies (n'=0 -> dot=0)
        for (int s = base + lane; s < pad; s += 32) {
            const int p = s >> 1, h = s & 1;
            g_xy[warp][p * 4 + h] = 0.f;  g_xy[warp][p * 4 + 2 + h] = 0.f;
            g_nn[warp][p * 4 + h] = 0.f;  g_nn[warp][p * 4 + 2 + h] = 0.f;
            g_dp[warp][p * 2 + h] = 0.f;
        }
        if (lane == 0) { g_cnt[warp] = base; g_npair[warp] = pad >> 1; }
    }
    if (tid == 0) g_ctr1 = 0;                 // reset for next replay
}

// ============================================================================
// Kernel 2: vote (all blocks) + final reduction (last-arriving block)
// ============================================================================
__global__ void __launch_bounds__(256) vote_final_kernel(const float* __restrict__ extents,
                                                         const float* __restrict__ poses,
                                                         const float* __restrict__ meta,
                                                         float* __restrict__ out)
{
    __shared__ __align__(16) P4     s_xy[1200];
    __shared__ __align__(16) P4     s_nn[1200];
    __shared__ __align__(16) float2 s_dp[1200];
    __shared__ unsigned s_old;

    const int cls = blockIdx.y;           // 0..6 (class cls+1)
    const int tid = threadIdx.x;
    const int lane = tid & 31, warp = tid >> 5;
    const int npair = g_npair[cls];

    const P4*     gxy = (const P4*)g_xy[cls];
    const P4*     gnn = (const P4*)g_nn[cls];
    const float2* gdp = (const float2*)g_dp[cls];
    for (int i = tid; i < npair; i += 256) { s_xy[i] = gxy[i]; s_nn[i] = gnn[i]; s_dp[i] = gdp[i]; }
    __syncthreads();

    const int loc = blockIdx.x * 256 + tid;
    const float gx = (float)(loc % IMW);
    const float gy = (float)(loc / IMW);
    const ull gx2 = pk2(gx, gx);
    const ull gy2 = pk2(gy, gy);

    int v = 0; float ds = 0.f;
    #pragma unroll 4
    for (int p = 0; p < npair; p++) {
        P4 axy = s_xy[p];
        P4 ann = s_nn[p];
        float2 dd = s_dp[p];
        ull dx2  = add2(gx2, axy.a);
        ull dy2  = add2(gy2, axy.b);
        ull dot2 = fma2(dy2, ann.b, mul2(dx2, ann.a));   // dot' = dot/0.9
        ull d22  = fma2(dy2, dy2, mul2(dx2, dx2));       // d2
        ull q2   = mul2(dot2, dot2);
        float dot0, dot1, q0, q1, e0, e1;
        up2(dot2, dot0, dot1); up2(q2, q0, q1); up2(d22, e0, e1);
        if (dot0 > 0.f && q0 > e0) { v++; ds += dd.x; }
        if (dot1 > 0.f && q1 > e1) { v++; ds += dd.y; }
    }

    // block-local argmax (max count, min loc on ties) — reuse smem
    __syncthreads();
    int*   rv = (int*)s_xy;
    int*   rl = (int*)s_nn;
    float* rd = (float*)s_dp;
    rv[tid] = v; rl[tid] = loc; rd[tid] = ds;
    __syncthreads();
    #pragma unroll
    for (int s = 128; s > 0; s >>= 1) {
        if (tid < s) {
            int ov = rv[tid + s], ol = rl[tid + s];
            if (ov > rv[tid] || (ov == rv[tid] && ol < rl[tid])) {
                rv[tid] = ov; rl[tid] = ol; rd[tid] = rd[tid + s];
            }
        }
        __syncthreads();
    }
    if (tid == 0) {
        g_pv [cls * NBLKX + blockIdx.x] = rv[0];
        g_pl [cls * NBLKX + blockIdx.x] = rl[0];
        g_pds[cls * NBLKX + blockIdx.x] = rd[0];
    }

    // ---- arrival: last block performs final reduction + outputs ----
    __threadfence();
    __syncthreads();
    if (tid == 0) s_old = atomicAdd(&g_ctr2, 1u);
    __syncthreads();
    if (s_old != (unsigned)(NBLKX * NCOBJ) - 1u) return;
    __threadfence();

    // warp c handles class c (0..7); class 0 never votes -> zeros path
    const int c = warp;
    float vmax = 0.f, dsum = 0.f, nv = 0.f;
    int best = 0;
    if (c > 0) {
        const int ci = c - 1;
        int bc = -1, bl = 0; float bd = 0.f;
        for (int j = lane; j < NBLKX; j += 32) {
            int   vv = g_pv [ci * NBLKX + j];
            int   ll = g_pl [ci * NBLKX + j];
            float dd = g_pds[ci * NBLKX + j];
            if (vv > bc || (vv == bc && ll < bl)) { bc = vv; bl = ll; bd = dd; }
        }
        #pragma unroll
        for (int off = 16; off > 0; off >>= 1) {
            int   ov = __shfl_down_sync(0xFFFFFFFFu, bc, off);
            int   ol = __shfl_down_sync(0xFFFFFFFFu, bl, off);
            float od = __shfl_down_sync(0xFFFFFFFFu, bd, off);
            if (ov > bc || (ov == bc && ol < bl)) { bc = ov; bl = ol; bd = od; }
        }
        vmax = (float)bc; best = bl; dsum = bd;
        nv = (float)g_cnt[ci];
    }

    if (lane == 0) {
        const float dbar = dsum / fmaxf(vmax, 1.f);
        const float cx = (float)(best % IMW);
        const float cy = (float)(best / IMW);
        const float fx = meta[0], px = meta[2], fy = meta[4], py = meta[5];
        const float e0 = extents[c * 3 + 0];
        const float e1 = extents[c * 3 + 1];
        const float e2 = extents[c * 3 + 2];
        const float diag = sqrtf(e0 * e0 + e1 * e1 + e2 * e2);
        const float safe = fmaxf(dbar, 1e-6f);
        const float bw = diag * fx / safe;
        const float bh = diag * fy / safe;
        const float score = vmax / fmaxf(nv, 1.f);

        float* box = out + c * 7;
        box[0] = 0.f;
        box[1] = (float)c;
        box[2] = cx - bw * 0.5f;
        box[3] = cy - bh * 0.5f;
        box[4] = cx + bw * 0.5f;
        box[5] = cy + bh * 0.5f;
        box[6] = score;

        float* pp = out + 56 + c * 7;
        pp[0] = poses[c * 7 + 0];
        pp[1] = poses[c * 7 + 1];
        pp[2] = poses[c * 7 + 2];
        pp[3] = poses[c * 7 + 3];
        pp[4] = (cx - px) * dbar / fmaxf(fx, 1e-6f);
        pp[5] = (cy - py) * dbar / fmaxf(fy, 1e-6f);
        pp[6] = dbar;
    }
    if (tid == 0) g_ctr2 = 0;                 // reset for next replay
}

// ============================================================================
extern "C" void kernel_launch(void* const* d_in, const int* in_sizes, int n_in,
                              void* d_out, int out_size)
{
    const int*   labels  = (const int*)d_in[0];
    const int*   masks   = (const int*)d_in[1];
    const float* vp      = (const float*)d_in[2];
    const float* extents = (const float*)d_in[3];
    const float* poses   = (const float*)d_in[4];
    const float* meta    = (const float*)d_in[5];
    float* out = (float*)d_out;

    stage_compact_kernel<<<NSTAGE, 256>>>(labels, masks, vp);
    vote_final_kernel<<<dim3(NBLKX, NCOBJ), 256>>>(extents, poses, meta, out);
}

// round 8
// speedup vs baseline: 1.3166x; 1.3166x over previous
#include <cuda_runtime.h>
#include <cuda_bf16.h>
#include <math.h>

#define HWSZ   19200
#define IMW    160
#define NPIX   2400
#define NBLKX  75          // 19200 / 256 cell blocks
#define NCOBJ  7           // object classes 1..7

typedef unsigned long long ull;

// ---------------- packed f32x2 helpers ----------------
__device__ __forceinline__ ull pk2(float lo, float hi) {
    ull r; asm("mov.b64 %0, {%1, %2};" : "=l"(r) : "f"(lo), "f"(hi)); return r;
}
__device__ __forceinline__ void up2(ull v, float& lo, float& hi) {
    asm("mov.b64 {%0, %1}, %2;" : "=f"(lo), "=f"(hi) : "l"(v));
}
__device__ __forceinline__ ull add2(ull a, ull b) {
    ull r; asm("add.rn.f32x2 %0, %1, %2;" : "=l"(r) : "l"(a), "l"(b)); return r;
}
__device__ __forceinline__ ull mul2(ull a, ull b) {
    ull r; asm("mul.rn.f32x2 %0, %1, %2;" : "=l"(r) : "l"(a), "l"(b)); return r;
}
__device__ __forceinline__ ull fma2(ull a, ull b, ull c) {
    ull r; asm("fma.rn.f32x2 %0, %1, %2, %3;" : "=l"(r) : "l"(a), "l"(b), "l"(c)); return r;
}

// ---------------- scratch ----------------
// pair p of class c: g_xy[c][4p..4p+3] = (-xs0,-xs1,-ys0,-ys1)
//                    g_nn[c][4p..4p+3] = (nx'0,nx'1,ny'0,ny'1)   nx' = nx/0.9
//                    g_dp[c][2p..2p+1] = (dep0, dep1)
__device__ __align__(16) float g_xy[NCOBJ][4800];
__device__ __align__(16) float g_nn[NCOBJ][4800];
__device__ __align__(8)  float g_dp[NCOBJ][2400];
__device__ int   g_cnt[NCOBJ];
__device__ int   g_npair[NCOBJ];
__device__ int   g_pv[NCOBJ * NBLKX];
__device__ int   g_pl[NCOBJ * NBLKX];
__device__ unsigned g_ctr = 0;                   // arrival counter (self-resetting)

struct P4 { ull a, b; };

// ============================================================================
// Kernel 1: prep — one 1024-thread block; batched loads -> SMEM staging ->
// warp-per-class ballot compaction from SMEM (no L2 round trip)
// ============================================================================
__global__ void __launch_bounds__(1024) prep_kernel(const int* __restrict__ labels,
                                                    const int* __restrict__ masks,
                                                    const float* __restrict__ vp)
{
    // s_rec[i] = { xy packed as 2xu16 in float bits, nx', ny', dep }
    __shared__ __align__(16) float4 s_rec[NPIX];   // 38400 B
    __shared__ int s_cls[NPIX];                    //  9600 B  (total 48000 <= 48K static)

    const int tid = threadIdx.x, lane = tid & 31, warp = tid >> 5;

    // ---- stage: batched loads, all math in parallel across 1024 threads ----
    int labv[3], mskv[3];
    #pragma unroll
    for (int k = 0; k < 3; k++) {
        int i = k * 1024 + tid;
        labv[k] = (i < NPIX) ? labels[i * 8] : 0;
    }
    #pragma unroll
    for (int k = 0; k < 3; k++) {
        int i = k * 1024 + tid;
        mskv[k] = (i < NPIX) ? masks[i * 8] : 0;
    }
    #pragma unroll
    for (int k = 0; k < 3; k++) {
        int i = k * 1024 + tid;
        if (i < NPIX) {
            const int c = (mskv[k] > 0 && labv[k] > 0) ? labv[k] : 0;
            s_cls[i] = c;
            if (c) {
                const int idx = i * 8;
                const float vx = vp[(c * 3 + 0) * HWSZ + idx];
                const float vy = vp[(c * 3 + 1) * HWSZ + idx];
                const float vz = vp[(c * 3 + 2) * HWSZ + idx];
                const float nrm = sqrtf(vx * vx + vy * vy) + 1e-6f;
                const float nxp = (vx / nrm) * (1.0f / 0.9f);
                const float nyp = (vy / nrm) * (1.0f / 0.9f);
                const unsigned xs = (unsigned)(idx % IMW);
                const unsigned ys = (unsigned)(idx / IMW);
                s_rec[i] = make_float4(__uint_as_float(xs | (ys << 16)), nxp, nyp, expf(vz));
            }
        }
    }
    __syncthreads();

    // ---- compact: warp w handles class w+1, reads SMEM only ----
    if (warp < NCOBJ) {
        const int myc = warp + 1;
        const unsigned below = (1u << lane) - 1u;
        int base = 0;
        #pragma unroll 5
        for (int it = 0; it < 75; it++) {
            const int i = it * 32 + lane;
            const bool pred = (s_cls[i] == myc);
            const unsigned bal = __ballot_sync(0xFFFFFFFFu, pred);
            if (pred) {
                const float4 r = s_rec[i];
                const unsigned xy = __float_as_uint(r.x);
                const float xs = (float)(xy & 0xFFFFu);
                const float ys = (float)(xy >> 16);
                const int slot = base + __popc(bal & below);
                const int p = slot >> 1, h = slot & 1;
                g_xy[warp][p * 4 + h]     = -xs;
                g_xy[warp][p * 4 + 2 + h] = -ys;
                g_nn[warp][p * 4 + h]     = r.y;
                g_nn[warp][p * 4 + 2 + h] = r.z;
                g_dp[warp][p * 2 + h]     = r.w;
            }
            base += __popc(bal);
        }
        const int pad = (base + 7) & ~7;      // pad: never-inlier dummies (n'=0 -> dot=0)
        for (int s = base + lane; s < pad; s += 32) {
            const int p = s >> 1, h = s & 1;
            g_xy[warp][p * 4 + h] = 0.f;  g_xy[warp][p * 4 + 2 + h] = 0.f;
            g_nn[warp][p * 4 + h] = 0.f;  g_nn[warp][p * 4 + 2 + h] = 0.f;
            g_dp[warp][p * 2 + h] = 0.f;
        }
        if (lane == 0) { g_cnt[warp] = base; g_npair[warp] = pad >> 1; }
    }
}

// ============================================================================
// Kernel 2: vote (counts only, no depth in inner loop) + final reduction with
// winner-depth recompute (last-arriving block)
// ============================================================================
__global__ void __launch_bounds__(256, 4) vote_final_kernel(const float* __restrict__ extents,
                                                            const float* __restrict__ poses,
                                                            const float* __restrict__ meta,
                                                            float* __restrict__ out)
{
    __shared__ __align__(16) P4 s_xy[1200];
    __shared__ __align__(16) P4 s_nn[1200];
    __shared__ unsigned s_old;

    const int cls = blockIdx.y;           // 0..6 (class cls+1)
    const int tid = threadIdx.x;
    const int lane = tid & 31, warp = tid >> 5;
    const int npair = g_npair[cls];

    const P4* gxy = (const P4*)g_xy[cls];
    const P4* gnn = (const P4*)g_nn[cls];
    for (int i = tid; i < npair; i += 256) { s_xy[i] = gxy[i]; s_nn[i] = gnn[i]; }
    __syncthreads();

    const int loc = blockIdx.x * 256 + tid;
    const float gx = (float)(loc % IMW);
    const float gy = (float)(loc / IMW);
    const ull gx2 = pk2(gx, gx);
    const ull gy2 = pk2(gy, gy);

    int v = 0;
    #pragma unroll 4
    for (int p = 0; p < npair; p++) {
        P4 axy = s_xy[p];
        P4 ann = s_nn[p];
        ull dx2  = add2(gx2, axy.a);
        ull dy2  = add2(gy2, axy.b);
        ull dot2 = fma2(dy2, ann.b, mul2(dx2, ann.a));   // dot' = dot/0.9
        ull d22  = fma2(dy2, dy2, mul2(dx2, dx2));       // d2
        ull q2   = mul2(dot2, dot2);
        float dot0, dot1, q0, q1, e0, e1;
        up2(dot2, dot0, dot1); up2(q2, q0, q1); up2(d22, e0, e1);
        if (dot0 > 0.f && q0 > e0) v++;
        if (dot1 > 0.f && q1 > e1) v++;
    }

    // block-local argmax (max count, min loc on ties) — reuse smem
    __syncthreads();
    int* rv = (int*)s_xy;
    int* rl = (int*)s_nn;
    rv[tid] = v; rl[tid] = loc;
    __syncthreads();
    #pragma unroll
    for (int s = 128; s > 0; s >>= 1) {
        if (tid < s) {
            int ov = rv[tid + s], ol = rl[tid + s];
            if (ov > rv[tid] || (ov == rv[tid] && ol < rl[tid])) { rv[tid] = ov; rl[tid] = ol; }
        }
        __syncthreads();
    }
    if (tid == 0) {
        g_pv[cls * NBLKX + blockIdx.x] = rv[0];
        g_pl[cls * NBLKX + blockIdx.x] = rl[0];
    }

    // ---- arrival: last block performs final reduction + outputs ----
    __threadfence();
    __syncthreads();
    if (tid == 0) s_old = atomicAdd(&g_ctr, 1u);
    __syncthreads();
    if (s_old != (unsigned)(NBLKX * NCOBJ) - 1u) return;
    __threadfence();

    // warp c handles class c (0..7); class 0 never votes -> zeros path
    const int c = warp;
    float vmax = 0.f, dsum = 0.f, nv = 0.f;
    int best = 0;
    if (c > 0) {
        const int ci = c - 1;
        int bc = -1, bl = 0;
        for (int j = lane; j < NBLKX; j += 32) {
            int vv = g_pv[ci * NBLKX + j];
            int ll = g_pl[ci * NBLKX + j];
            if (vv > bc || (vv == bc && ll < bl)) { bc = vv; bl = ll; }
        }
        #pragma unroll
        for (int off = 16; off > 0; off >>= 1) {
            int ov = __shfl_down_sync(0xFFFFFFFFu, bc, off);
            int ol = __shfl_down_sync(0xFFFFFFFFu, bl, off);
            if (ov > bc || (ov == bc && ol < bl)) { bc = ov; bl = ol; }
        }
        bc = __shfl_sync(0xFFFFFFFFu, bc, 0);
        bl = __shfl_sync(0xFFFFFFFFu, bl, 0);

        // recompute depth sum at the winning cell (same ops as packed lanes =>
        // identical rounding; fixed lane-stride + shuffle tree => deterministic)
        const float wx = (float)(bl % IMW);
        const float wy = (float)(bl / IMW);
        const int npx = g_npair[ci] * 2;
        float ds = 0.f;
        for (int j = lane; j < npx; j += 32) {
            const int p = j >> 1, h = j & 1;
            const float mxs = g_xy[ci][p * 4 + h];
            const float mys = g_xy[ci][p * 4 + 2 + h];
            const float nx  = g_nn[ci][p * 4 + h];
            const float ny  = g_nn[ci][p * 4 + 2 + h];
            const float dx = wx + mxs;
            const float dy = wy + mys;
            const float dot = fmaf(dy, ny, dx * nx);
            const float d2  = fmaf(dy, dy, dx * dx);
            if (dot > 0.f && dot * dot > d2) ds += g_dp[ci][p * 2 + h];
        }
        #pragma unroll
        for (int off = 16; off > 0; off >>= 1)
            ds += __shfl_down_sync(0xFFFFFFFFu, ds, off);

        vmax = (float)bc; best = bl; dsum = ds;
        nv = (float)g_cnt[ci];
    }

    if (lane == 0) {
        const float dbar = dsum / fmaxf(vmax, 1.f);
        const float cx = (float)(best % IMW);
        const float cy = (float)(best / IMW);
        const float fx = meta[0], px = meta[2], fy = meta[4], py = meta[5];
        const float e0 = extents[c * 3 + 0];
        const float e1 = extents[c * 3 + 1];
        const float e2 = extents[c * 3 + 2];
        const float diag = sqrtf(e0 * e0 + e1 * e1 + e2 * e2);
        const float safe = fmaxf(dbar, 1e-6f);
        const float bw = diag * fx / safe;
        const float bh = diag * fy / safe;
        const float score = vmax / fmaxf(nv, 1.f);

        float* box = out + c * 7;
        box[0] = 0.f;
        box[1] = (float)c;
        box[2] = cx - bw * 0.5f;
        box[3] = cy - bh * 0.5f;
        box[4] = cx + bw * 0.5f;
        box[5] = cy + bh * 0.5f;
        box[6] = score;

        float* pp = out + 56 + c * 7;
        pp[0] = poses[c * 7 + 0];
        pp[1] = poses[c * 7 + 1];
        pp[2] = poses[c * 7 + 2];
        pp[3] = poses[c * 7 + 3];
        pp[4] = (cx - px) * dbar / fmaxf(fx, 1e-6f);
        pp[5] = (cy - py) * dbar / fmaxf(fy, 1e-6f);
        pp[6] = dbar;
    }
    if (tid == 0) g_ctr = 0;                  // reset for next replay
}

// ============================================================================
extern "C" void kernel_launch(void* const* d_in, const int* in_sizes, int n_in,
                              void* d_out, int out_size)
{
    const int*   labels  = (const int*)d_in[0];
    const int*   masks   = (const int*)d_in[1];
    const float* vp      = (const float*)d_in[2];
    const float* extents = (const float*)d_in[3];
    const float* poses   = (const float*)d_in[4];
    const float* meta    = (const float*)d_in[5];
    float* out = (float*)d_out;

    prep_kernel<<<1, 1024>>>(labels, masks, vp);
    vote_final_kernel<<<dim3(NBLKX, NCOBJ), 256>>>(extents, poses, meta, out);
}